// round 1
// baseline (speedup 1.0000x reference)
#include <cuda_runtime.h>
#include <math.h>

#define B_  2
#define L_  4096
#define C_  512
#define H_  8
#define HD_ 64
#define M_  (B_*L_)   // 8192

// Scratch (allocation-free rule: device globals)
__device__ float g_q[B_*H_*L_*HD_];
__device__ float g_k[B_*H_*L_*HD_];
__device__ float g_v[B_*H_*L_*HD_];
__device__ float g_ctx[M_*C_];

// ---------------------------------------------------------------------------
// Kernel 1: QKV GEMM (y = x @ W^T + b) with fused RoPE epilogue.
// M=8192, N=1536, K=512. BM=BN=64, BK=16, 256 threads, 4x4 microtile.
// ---------------------------------------------------------------------------
__global__ void __launch_bounds__(256) qkv_rope_kernel(
    const float* __restrict__ x, const float* __restrict__ w,
    const float* __restrict__ bias)
{
    __shared__ float As[16][64];   // [k][row]
    __shared__ float Bs[16][64];   // [k][col]
    const int bm = blockIdx.y, bn = blockIdx.x;
    const int tid = threadIdx.x;
    const int tr = tid >> 4, tc = tid & 15;
    const int lrow = tid >> 2;
    const int lc4  = (tid & 3) * 4;
    const float* xrow = x + (size_t)(bm * 64 + lrow) * C_;
    const float* wrow = w + (size_t)(bn * 64 + lrow) * C_;

    float acc[4][4] = {};
    for (int k0 = 0; k0 < C_; k0 += 16) {
        float4 av = *(const float4*)(xrow + k0 + lc4);
        float4 bv = *(const float4*)(wrow + k0 + lc4);
        __syncthreads();
        As[lc4+0][lrow] = av.x; As[lc4+1][lrow] = av.y;
        As[lc4+2][lrow] = av.z; As[lc4+3][lrow] = av.w;
        Bs[lc4+0][lrow] = bv.x; Bs[lc4+1][lrow] = bv.y;
        Bs[lc4+2][lrow] = bv.z; Bs[lc4+3][lrow] = bv.w;
        __syncthreads();
        #pragma unroll
        for (int kk = 0; kk < 16; kk++) {
            float4 a  = *(const float4*)&As[kk][tr*4];
            float4 bq = *(const float4*)&Bs[kk][tc*4];
            float av_[4] = {a.x, a.y, a.z, a.w};
            float bv_[4] = {bq.x, bq.y, bq.z, bq.w};
            #pragma unroll
            for (int i = 0; i < 4; i++)
                #pragma unroll
                for (int j = 0; j < 4; j++)
                    acc[i][j] += av_[i] * bv_[j];
        }
    }

    const int gc0  = bn * 64 + tc * 4;
    const int which = gc0 >> 9;        // 0=q 1=k 2=v (whole 4-col group, gc0%4==0)
    const int cmod  = gc0 & 511;
    const int h  = cmod >> 6;
    const int d0 = cmod & 63;

    float invfv[4];
    if (which < 2) {
        #pragma unroll
        for (int j = 0; j < 4; j++) {
            int d = d0 + j;
            // inv_freq[j'] = 10000^(-j'/32), j' = d mod 32
            invfv[j] = (float)exp(-(double)(d & 31) * 0.28782313662425574);
        }
    }

    #pragma unroll
    for (int i = 0; i < 4; i++) {
        int row = bm * 64 + tr * 4 + i;
        int b = row >> 12;
        int l = row & (L_ - 1);
        float v0 = acc[i][0] + bias[gc0+0];
        float v1 = acc[i][1] + bias[gc0+1];
        float v2 = acc[i][2] + bias[gc0+2];
        float v3 = acc[i][3] + bias[gc0+3];
        size_t base = ((size_t)(b * H_ + h) * L_ + l) * HD_ + d0;
        if (which == 2) {
            g_v[base+0] = v0; g_v[base+1] = v1; g_v[base+2] = v2; g_v[base+3] = v3;
        } else {
            float fl = (float)l;
            float a0 = fl * invfv[0], a1 = fl * invfv[1];
            float a2 = fl * invfv[2], a3 = fl * invfv[3];
            float o0 = v0 * cosf(a0) - v1 * sinf(a0);
            float o1 = v1 * cosf(a1) + v0 * sinf(a1);
            float o2 = v2 * cosf(a2) - v3 * sinf(a2);
            float o3 = v3 * cosf(a3) + v2 * sinf(a3);
            float* dst = (which == 0) ? g_q : g_k;
            dst[base+0] = o0; dst[base+1] = o1; dst[base+2] = o2; dst[base+3] = o3;
        }
    }
}

// ---------------------------------------------------------------------------
// Kernel 2: flash attention. One block = one (b, h, 64-row q tile).
// 256 threads; thread (tr,tc) owns rows r0..r0+3, cols c0..c0+3.
// ---------------------------------------------------------------------------
#define ATTN_SMEM_FLOATS (3*64*64 + 64*65)
#define ATTN_SMEM_BYTES  (ATTN_SMEM_FLOATS * 4)

__global__ void __launch_bounds__(256) attn_kernel()
{
    extern __shared__ float smem[];
    float (*Qs)[64] = (float(*)[64])(smem);             // [d][row], pre-scaled
    float (*Ks)[64] = (float(*)[64])(smem + 4096);      // [d][col]
    float (*Vs)[64] = (float(*)[64])(smem + 8192);      // [key][d]
    float (*Ps)[65] = (float(*)[65])(smem + 12288);     // [key][row], padded

    const int qt = blockIdx.x, h = blockIdx.y, b = blockIdx.z;
    const int tid = threadIdx.x;
    const int tr = tid >> 4, tc = tid & 15;
    const int r0 = tr * 4, c0 = tc * 4;
    const int lr = tid >> 4;
    const int lc = (tid & 15) * 4;

    const float* qg = g_q + ((size_t)(b * H_ + h) * L_ + qt * 64) * HD_;
    const float* kg = g_k + (size_t)(b * H_ + h) * L_ * HD_;
    const float* vg = g_v + (size_t)(b * H_ + h) * L_ * HD_;

    // Load Q transposed, fold in the 1/sqrt(hd)=0.125 scale
    #pragma unroll
    for (int it = 0; it < 4; it++) {
        int row = it * 16 + lr;
        float4 qv = *(const float4*)(qg + row * HD_ + lc);
        Qs[lc+0][row] = qv.x * 0.125f; Qs[lc+1][row] = qv.y * 0.125f;
        Qs[lc+2][row] = qv.z * 0.125f; Qs[lc+3][row] = qv.w * 0.125f;
    }

    float o[4][4] = {};
    float mrow[4] = {-INFINITY, -INFINITY, -INFINITY, -INFINITY};
    float lsumr[4] = {};

    for (int kt = 0; kt < L_ / 64; kt++) {
        float4 kreg[4], vreg[4];
        #pragma unroll
        for (int it = 0; it < 4; it++) {
            int row = kt * 64 + it * 16 + lr;
            kreg[it] = *(const float4*)(kg + row * HD_ + lc);
            vreg[it] = *(const float4*)(vg + row * HD_ + lc);
        }
        __syncthreads();   // previous iteration done reading Ks/Vs/Ps
        #pragma unroll
        for (int it = 0; it < 4; it++) {
            int row = it * 16 + lr;
            Ks[lc+0][row] = kreg[it].x; Ks[lc+1][row] = kreg[it].y;
            Ks[lc+2][row] = kreg[it].z; Ks[lc+3][row] = kreg[it].w;
            *(float4*)&Vs[row][lc] = vreg[it];
        }
        __syncthreads();

        // S = (Q*scale) @ K^T for this tile
        float s[4][4] = {};
        #pragma unroll 8
        for (int kk = 0; kk < 64; kk++) {
            float4 a  = *(const float4*)&Qs[kk][r0];
            float4 bq = *(const float4*)&Ks[kk][c0];
            float av_[4] = {a.x, a.y, a.z, a.w};
            float bv_[4] = {bq.x, bq.y, bq.z, bq.w};
            #pragma unroll
            for (int i = 0; i < 4; i++)
                #pragma unroll
                for (int j = 0; j < 4; j++)
                    s[i][j] += av_[i] * bv_[j];
        }

        // Online softmax (row stats shared by the 16 threads of each row group)
        #pragma unroll
        for (int i = 0; i < 4; i++) {
            float mt = fmaxf(fmaxf(s[i][0], s[i][1]), fmaxf(s[i][2], s[i][3]));
            #pragma unroll
            for (int msk = 8; msk; msk >>= 1)
                mt = fmaxf(mt, __shfl_xor_sync(0xffffffffu, mt, msk));
            float mnew = fmaxf(mrow[i], mt);
            float alpha = expf(mrow[i] - mnew);
            mrow[i] = mnew;
            float ls = 0.f;
            #pragma unroll
            for (int j = 0; j < 4; j++) {
                s[i][j] = expf(s[i][j] - mnew);
                ls += s[i][j];
            }
            #pragma unroll
            for (int msk = 8; msk; msk >>= 1)
                ls += __shfl_xor_sync(0xffffffffu, ls, msk);
            lsumr[i] = lsumr[i] * alpha + ls;
            #pragma unroll
            for (int j = 0; j < 4; j++) o[i][j] *= alpha;
            // stage P transposed: Ps[key][row]
            #pragma unroll
            for (int j = 0; j < 4; j++) Ps[c0+j][r0+i] = s[i][j];
        }
        __syncthreads();

        // O += P @ V
        #pragma unroll 8
        for (int kk = 0; kk < 64; kk++) {
            float p0 = Ps[kk][r0+0], p1 = Ps[kk][r0+1];
            float p2 = Ps[kk][r0+2], p3 = Ps[kk][r0+3];
            float4 vv = *(const float4*)&Vs[kk][c0];
            o[0][0] += p0*vv.x; o[0][1] += p0*vv.y; o[0][2] += p0*vv.z; o[0][3] += p0*vv.w;
            o[1][0] += p1*vv.x; o[1][1] += p1*vv.y; o[1][2] += p1*vv.z; o[1][3] += p1*vv.w;
            o[2][0] += p2*vv.x; o[2][1] += p2*vv.y; o[2][2] += p2*vv.z; o[2][3] += p2*vv.w;
            o[3][0] += p3*vv.x; o[3][1] += p3*vv.y; o[3][2] += p3*vv.z; o[3][3] += p3*vv.w;
        }
    }

    // normalize + write to ctx in [b][l][h*64+d] layout
    #pragma unroll
    for (int i = 0; i < 4; i++) {
        float inv = 1.0f / lsumr[i];
        int lidx = qt * 64 + r0 + i;
        float4 ov = make_float4(o[i][0]*inv, o[i][1]*inv, o[i][2]*inv, o[i][3]*inv);
        *(float4*)(g_ctx + ((size_t)b * L_ + lidx) * C_ + h * HD_ + c0) = ov;
    }
}

// ---------------------------------------------------------------------------
// Kernel 3: output projection (out = ctx @ proj_w^T + proj_b). M=8192, N=K=512.
// ---------------------------------------------------------------------------
__global__ void __launch_bounds__(256) proj_kernel(
    const float* __restrict__ w, const float* __restrict__ bias,
    float* __restrict__ out)
{
    __shared__ float As[16][64];
    __shared__ float Bs[16][64];
    const int bm = blockIdx.y, bn = blockIdx.x;
    const int tid = threadIdx.x;
    const int tr = tid >> 4, tc = tid & 15;
    const int lrow = tid >> 2;
    const int lc4  = (tid & 3) * 4;
    const float* xrow = g_ctx + (size_t)(bm * 64 + lrow) * C_;
    const float* wrow = w + (size_t)(bn * 64 + lrow) * C_;

    float acc[4][4] = {};
    for (int k0 = 0; k0 < C_; k0 += 16) {
        float4 av = *(const float4*)(xrow + k0 + lc4);
        float4 bv = *(const float4*)(wrow + k0 + lc4);
        __syncthreads();
        As[lc4+0][lrow] = av.x; As[lc4+1][lrow] = av.y;
        As[lc4+2][lrow] = av.z; As[lc4+3][lrow] = av.w;
        Bs[lc4+0][lrow] = bv.x; Bs[lc4+1][lrow] = bv.y;
        Bs[lc4+2][lrow] = bv.z; Bs[lc4+3][lrow] = bv.w;
        __syncthreads();
        #pragma unroll
        for (int kk = 0; kk < 16; kk++) {
            float4 a  = *(const float4*)&As[kk][tr*4];
            float4 bq = *(const float4*)&Bs[kk][tc*4];
            float av_[4] = {a.x, a.y, a.z, a.w};
            float bv_[4] = {bq.x, bq.y, bq.z, bq.w};
            #pragma unroll
            for (int i = 0; i < 4; i++)
                #pragma unroll
                for (int j = 0; j < 4; j++)
                    acc[i][j] += av_[i] * bv_[j];
        }
    }

    const int gc0 = bn * 64 + tc * 4;
    #pragma unroll
    for (int i = 0; i < 4; i++) {
        int row = bm * 64 + tr * 4 + i;
        float4 ov = make_float4(acc[i][0] + bias[gc0+0],
                                acc[i][1] + bias[gc0+1],
                                acc[i][2] + bias[gc0+2],
                                acc[i][3] + bias[gc0+3]);
        *(float4*)(out + (size_t)row * C_ + gc0) = ov;
    }
}

// ---------------------------------------------------------------------------
extern "C" void kernel_launch(void* const* d_in, const int* in_sizes, int n_in,
                              void* d_out, int out_size)
{
    const float* x      = (const float*)d_in[0];
    const float* qkv_w  = (const float*)d_in[1];
    const float* qkv_b  = (const float*)d_in[2];
    const float* proj_w = (const float*)d_in[3];
    const float* proj_b = (const float*)d_in[4];
    float* out = (float*)d_out;

    cudaFuncSetAttribute(attn_kernel,
                         cudaFuncAttributeMaxDynamicSharedMemorySize,
                         ATTN_SMEM_BYTES);

    qkv_rope_kernel<<<dim3(24, 128), 256>>>(x, qkv_w, qkv_b);
    attn_kernel<<<dim3(L_/64, H_, B_), 256, ATTN_SMEM_BYTES>>>();
    proj_kernel<<<dim3(8, 128), 256>>>(proj_w, proj_b, out);
}

// round 2
// speedup vs baseline: 3.6753x; 3.6753x over previous
#include <cuda_runtime.h>
#include <math.h>

#define B_  2
#define L_  4096
#define C_  512
#define H_  8
#define HD_ 64

// Scratch (allocation-free rule: device globals)
__device__ float g_q[B_*H_*L_*HD_];          // [b][h][l][d]
__device__ float g_k[B_*H_*L_*HD_];          // [b][h][l][d]
__device__ float g_v[B_*H_*L_*HD_];          // TRANSPOSED: [b][h][d][l]
__device__ float g_ctx[B_*L_*C_];

// ---------------------------------------------------------------------------
// tf32 helpers
// ---------------------------------------------------------------------------
__device__ __forceinline__ unsigned f2tf(float f) {
    unsigned u; asm("cvt.rna.tf32.f32 %0, %1;" : "=r"(u) : "f"(f)); return u;
}
__device__ __forceinline__ void mma8(float c[4], const unsigned a[4], const unsigned b[2]) {
    asm volatile(
      "mma.sync.aligned.m16n8k8.row.col.f32.tf32.tf32.f32 "
      "{%0,%1,%2,%3}, {%4,%5,%6,%7}, {%8,%9}, {%0,%1,%2,%3};"
      : "+f"(c[0]), "+f"(c[1]), "+f"(c[2]), "+f"(c[3])
      : "r"(a[0]), "r"(a[1]), "r"(a[2]), "r"(a[3]), "r"(b[0]), "r"(b[1]));
}

// ---------------------------------------------------------------------------
// GEMM: out[M,N] = A[M,512] @ W[N,512]^T + bias.  MODE 0: qkv(+RoPE), 1: proj.
// Block tile 128x64, BK=32, 256 threads (8 warps: 4 m-warps x 2 n-warps),
// warp tile m32 x n32. Fragment loads are bank-conflict-free (stride 36).
// ---------------------------------------------------------------------------
template<int MODE>
__global__ void __launch_bounds__(256) mm_kernel(
    const float* __restrict__ Ain, const float* __restrict__ W,
    const float* __restrict__ bias, float* __restrict__ out)
{
    __shared__ unsigned As[128*36];
    __shared__ unsigned Bs[64*36];
    const int tid = threadIdx.x;
    const int bm = blockIdx.y, bn = blockIdx.x;
    const int lane = tid & 31, wid = tid >> 5;
    const int wm = wid >> 1, wn = wid & 1;
    const int g = lane >> 2, t = lane & 3;

    const float* A = (MODE == 1) ? (const float*)g_ctx : Ain;
    const int srow = tid >> 3, sc = (tid & 7) * 4;
    const float* ap = A + (size_t)(bm*128 + srow)*C_ + sc;
    const float* bp = W + (size_t)(bn*64 + srow)*C_ + sc;

    float acc[2][4][4];
    #pragma unroll
    for (int i=0;i<2;i++) for (int j=0;j<4;j++) for (int k=0;k<4;k++) acc[i][j][k]=0.f;

    for (int k0 = 0; k0 < C_; k0 += 32) {
        float4 ar[4], br[2];
        #pragma unroll
        for (int i=0;i<4;i++) ar[i] = *(const float4*)(ap + (size_t)i*32*C_ + k0);
        #pragma unroll
        for (int i=0;i<2;i++) br[i] = *(const float4*)(bp + (size_t)i*32*C_ + k0);
        __syncthreads();
        #pragma unroll
        for (int i=0;i<4;i++)
            *(uint4*)&As[(srow + i*32)*36 + sc] =
                make_uint4(f2tf(ar[i].x), f2tf(ar[i].y), f2tf(ar[i].z), f2tf(ar[i].w));
        #pragma unroll
        for (int i=0;i<2;i++)
            *(uint4*)&Bs[(srow + i*32)*36 + sc] =
                make_uint4(f2tf(br[i].x), f2tf(br[i].y), f2tf(br[i].z), f2tf(br[i].w));
        __syncthreads();
        #pragma unroll
        for (int kk=0;kk<4;kk++) {
            unsigned af[2][4], bf[4][2];
            #pragma unroll
            for (int mt=0;mt<2;mt++){
                int base = (wm*32 + mt*16 + g)*36 + kk*8 + t;
                af[mt][0]=As[base];       af[mt][1]=As[base+8*36];
                af[mt][2]=As[base+4];     af[mt][3]=As[base+8*36+4];
            }
            #pragma unroll
            for (int nt=0;nt<4;nt++){
                int base = (wn*32 + nt*8 + g)*36 + kk*8 + t;
                bf[nt][0]=Bs[base];       bf[nt][1]=Bs[base+4];
            }
            #pragma unroll
            for (int mt=0;mt<2;mt++)
                #pragma unroll
                for (int nt=0;nt<4;nt++) mma8(acc[mt][nt], af[mt], bf[nt]);
        }
    }

    // epilogue: thread owns cols {cc, cc+1} (a RoPE pair) for rows g/g+8 x 2 mtiles
    #pragma unroll
    for (int nt=0;nt<4;nt++){
        const int cc = bn*64 + wn*32 + nt*8 + 2*t;
        const float b0v = bias[cc], b1v = bias[cc+1];
        if (MODE == 1) {
            #pragma unroll
            for (int mt=0;mt<2;mt++)
                #pragma unroll
                for (int hf=0;hf<2;hf++){
                    int r = bm*128 + wm*32 + mt*16 + hf*8 + g;
                    float2 v = make_float2(acc[mt][nt][hf*2]+b0v, acc[mt][nt][hf*2+1]+b1v);
                    *(float2*)(out + (size_t)r*C_ + cc) = v;
                }
        } else {
            const int which = cc >> 9;           // 0=q 1=k 2=v
            const int h = (cc >> 6) & 7;
            const int d = cc & 63;               // even
            float invf0 = 0.f, invf1 = 0.f;
            if (which < 2) {
                invf0 = (float)exp(-(double)(d & 31)       * 0.28782313662425574);
                invf1 = (float)exp(-(double)((d & 31) + 1) * 0.28782313662425574);
            }
            #pragma unroll
            for (int mt=0;mt<2;mt++)
                #pragma unroll
                for (int hf=0;hf<2;hf++){
                    int r = bm*128 + wm*32 + mt*16 + hf*8 + g;
                    int bb = r >> 12, l = r & (L_-1);
                    float v0 = acc[mt][nt][hf*2]   + b0v;
                    float v1 = acc[mt][nt][hf*2+1] + b1v;
                    if (which == 2) {
                        float* vb = g_v + ((size_t)(bb*H_+h)*HD_ + d)*L_ + l;
                        vb[0]  = v0;
                        vb[L_] = v1;
                    } else {
                        float fl = (float)l;
                        float a0 = fl*invf0, a1 = fl*invf1;
                        float o0 = v0*cosf(a0) - v1*sinf(a0);
                        float o1 = v1*cosf(a1) + v0*sinf(a1);
                        float* dst = (which==0) ? g_q : g_k;
                        size_t base = ((size_t)(bb*H_+h)*L_ + l)*HD_ + d;
                        dst[base]   = o0;
                        dst[base+1] = o1;
                    }
                }
        }
    }
}

// ---------------------------------------------------------------------------
// Flash attention, tf32 MMA. Block = (b,h,128-row q tile), 128 threads (4 warps).
// Warp w owns rows [w*32, w*32+32). Smem arrays use stride 68 words ->
// fragment-load bank = (4g+t)%32 + const: conflict-free.
// ---------------------------------------------------------------------------
#define ATTN_SMEM_BYTES ((128+64+64+128)*68*4)   // 104448

__global__ void __launch_bounds__(128) attn_kernel()
{
    extern __shared__ unsigned sm[];
    unsigned* Qs = sm;                 // [128][68]  (Q * 0.125, tf32)
    unsigned* Ks = Qs + 128*68;        // [64][68]   [key][d]
    unsigned* Vt = Ks + 64*68;         // [64][68]   [d][key]
    unsigned* Ps = Vt + 64*68;         // [128][68]  [row][key]

    const int qt = blockIdx.x, h = blockIdx.y, b = blockIdx.z;
    const int tid = threadIdx.x, lane = tid & 31, wid = tid >> 5;
    const int g = lane >> 2, t = lane & 3;

    const float* qg  = g_q + ((size_t)(b*H_+h)*L_ + qt*128)*HD_;
    const float* kg  = g_k + (size_t)(b*H_+h)*L_*HD_;
    const float* vtg = g_v + (size_t)(b*H_+h)*HD_*L_;   // [d][l]

    // stage Q (scaled, tf32)
    #pragma unroll
    for (int i=0;i<16;i++){
        int idx = i*128 + tid;
        int r = idx >> 4, c = (idx & 15) * 4;
        float4 v = *(const float4*)(qg + r*HD_ + c);
        *(uint4*)&Qs[r*68 + c] = make_uint4(f2tf(v.x*0.125f), f2tf(v.y*0.125f),
                                            f2tf(v.z*0.125f), f2tf(v.w*0.125f));
    }

    float o[2][8][4];
    #pragma unroll
    for (int i=0;i<2;i++) for (int j=0;j<8;j++) for (int k=0;k<4;k++) o[i][j][k]=0.f;
    float mrow[4] = {-1e30f,-1e30f,-1e30f,-1e30f};
    float lrow[4] = {0.f,0.f,0.f,0.f};

    for (int kt = 0; kt < L_/64; kt++) {
        __syncthreads();   // previous tile's MMA reads of Ks/Vt done
        #pragma unroll
        for (int i=0;i<8;i++){
            int idx = i*128 + tid;
            int r = idx >> 4, c = (idx & 15) * 4;
            float4 kv = *(const float4*)(kg + (size_t)(kt*64 + r)*HD_ + c);
            *(uint4*)&Ks[r*68 + c] = make_uint4(f2tf(kv.x),f2tf(kv.y),f2tf(kv.z),f2tf(kv.w));
            float4 vv = *(const float4*)(vtg + (size_t)r*L_ + kt*64 + c);
            *(uint4*)&Vt[r*68 + c] = make_uint4(f2tf(vv.x),f2tf(vv.y),f2tf(vv.z),f2tf(vv.w));
        }
        __syncthreads();

        // ---- S = Q @ K^T ----
        float s[2][8][4];
        #pragma unroll
        for (int i=0;i<2;i++) for (int j=0;j<8;j++) for (int k=0;k<4;k++) s[i][j][k]=0.f;
        #pragma unroll
        for (int kk=0;kk<8;kk++){
            unsigned af[2][4], bf[8][2];
            #pragma unroll
            for (int mt=0;mt<2;mt++){
                int base = (wid*32 + mt*16 + g)*68 + kk*8 + t;
                af[mt][0]=Qs[base];     af[mt][1]=Qs[base+8*68];
                af[mt][2]=Qs[base+4];   af[mt][3]=Qs[base+8*68+4];
            }
            #pragma unroll
            for (int nt=0;nt<8;nt++){
                int nb = (nt*8 + g)*68 + kk*8 + t;
                bf[nt][0]=Ks[nb];       bf[nt][1]=Ks[nb+4];
            }
            #pragma unroll
            for (int mt=0;mt<2;mt++)
                #pragma unroll
                for (int nt=0;nt<8;nt++) mma8(s[mt][nt], af[mt], bf[nt]);
        }

        // ---- online softmax on C-fragments (row slots: mt*2+hf) ----
        #pragma unroll
        for (int mt=0;mt<2;mt++)
        #pragma unroll
        for (int hf=0;hf<2;hf++){
            int si = mt*2 + hf;
            float mx = -1e30f;
            #pragma unroll
            for (int nt=0;nt<8;nt++)
                mx = fmaxf(mx, fmaxf(s[mt][nt][hf*2], s[mt][nt][hf*2+1]));
            mx = fmaxf(mx, __shfl_xor_sync(0xffffffffu, mx, 1));
            mx = fmaxf(mx, __shfl_xor_sync(0xffffffffu, mx, 2));
            float mnew  = fmaxf(mrow[si], mx);
            float alpha = __expf(mrow[si] - mnew);
            mrow[si] = mnew;
            float ls = 0.f;
            #pragma unroll
            for (int nt=0;nt<8;nt++){
                float e0 = __expf(s[mt][nt][hf*2]   - mnew);
                float e1 = __expf(s[mt][nt][hf*2+1] - mnew);
                s[mt][nt][hf*2] = e0; s[mt][nt][hf*2+1] = e1;
                ls += e0 + e1;
            }
            ls += __shfl_xor_sync(0xffffffffu, ls, 1);
            ls += __shfl_xor_sync(0xffffffffu, ls, 2);
            lrow[si] = lrow[si]*alpha + ls;
            #pragma unroll
            for (int nt=0;nt<8;nt++){
                o[mt][nt][hf*2]   *= alpha;
                o[mt][nt][hf*2+1] *= alpha;
            }
        }

        // ---- stage P (own m-band only -> warp-local dependency) ----
        #pragma unroll
        for (int mt=0;mt<2;mt++)
            #pragma unroll
            for (int nt=0;nt<8;nt++){
                int row = wid*32 + mt*16 + g;
                *(uint2*)&Ps[row*68     + nt*8 + 2*t] =
                    make_uint2(f2tf(s[mt][nt][0]), f2tf(s[mt][nt][1]));
                *(uint2*)&Ps[(row+8)*68 + nt*8 + 2*t] =
                    make_uint2(f2tf(s[mt][nt][2]), f2tf(s[mt][nt][3]));
            }
        __syncwarp();

        // ---- O += P @ V  (B operand = Vt[d][key]) ----
        #pragma unroll
        for (int kk=0;kk<8;kk++){
            unsigned af[2][4], bf[8][2];
            #pragma unroll
            for (int mt=0;mt<2;mt++){
                int base = (wid*32 + mt*16 + g)*68 + kk*8 + t;
                af[mt][0]=Ps[base];     af[mt][1]=Ps[base+8*68];
                af[mt][2]=Ps[base+4];   af[mt][3]=Ps[base+8*68+4];
            }
            #pragma unroll
            for (int nt=0;nt<8;nt++){
                int nb = (nt*8 + g)*68 + kk*8 + t;
                bf[nt][0]=Vt[nb];       bf[nt][1]=Vt[nb+4];
            }
            #pragma unroll
            for (int mt=0;mt<2;mt++)
                #pragma unroll
                for (int nt=0;nt<8;nt++) mma8(o[mt][nt], af[mt], bf[nt]);
        }
    }

    // normalize + write ctx [b][l][h*64+d]
    #pragma unroll
    for (int mt=0;mt<2;mt++)
    #pragma unroll
    for (int hf=0;hf<2;hf++){
        int si = mt*2 + hf;
        float inv = 1.0f / lrow[si];
        int r = qt*128 + wid*32 + mt*16 + hf*8 + g;
        #pragma unroll
        for (int nt=0;nt<8;nt++){
            float2 v = make_float2(o[mt][nt][hf*2]*inv, o[mt][nt][hf*2+1]*inv);
            *(float2*)(g_ctx + ((size_t)b*L_ + r)*C_ + h*HD_ + nt*8 + 2*t) = v;
        }
    }
}

// ---------------------------------------------------------------------------
extern "C" void kernel_launch(void* const* d_in, const int* in_sizes, int n_in,
                              void* d_out, int out_size)
{
    const float* x      = (const float*)d_in[0];
    const float* qkv_w  = (const float*)d_in[1];
    const float* qkv_b  = (const float*)d_in[2];
    const float* proj_w = (const float*)d_in[3];
    const float* proj_b = (const float*)d_in[4];
    float* out = (float*)d_out;

    cudaFuncSetAttribute(attn_kernel,
                         cudaFuncAttributeMaxDynamicSharedMemorySize,
                         ATTN_SMEM_BYTES);

    mm_kernel<0><<<dim3(24, 64), 256>>>(x, qkv_w, qkv_b, nullptr);
    attn_kernel<<<dim3(L_/128, H_, B_), 128, ATTN_SMEM_BYTES>>>();
    mm_kernel<1><<<dim3(8, 64), 256>>>(nullptr, proj_w, proj_b, out);
}